// round 8
// baseline (speedup 1.0000x reference)
#include <cuda_runtime.h>
#include <cuda_fp16.h>
#include <math.h>
#include <stdint.h>

#define Lq 4096
#define Dq 1024
#define Hq 16
#define HDq 64
#define Mq 4096

// ---------------- scratch (device globals; no allocation allowed) ----------
__device__ float  g_h    [Lq*Dq];            // fp32 residual+attn@w_o
__device__ __half g_qkvh [Lq*3*Dq];          // half qkv (rope fused in epilogue)
__device__ __half g_xlnh [Lq*Dq];
__device__ __half g_ylnh [Lq*Dq];
__device__ __half g_attnh[Lq*Dq];
__device__ __half g_fc0h [(size_t)Lq*Mq];
// half weights, original [K][N] layout (convert only, no transpose)
__device__ __half g_wqkvc[Dq*3*Dq];
__device__ __half g_woc  [Dq*Dq];
__device__ __half g_fc0c [(size_t)Dq*Mq];
__device__ __half g_fc1c [(size_t)Mq*Dq];

// ---------------- helpers ----------------------------------------------------
__device__ __forceinline__ uint32_t smem_u32(const void* p) {
    uint32_t a;
    asm("{ .reg .u64 t; cvta.to.shared.u64 t, %1; cvt.u32.u64 %0, t; }" : "=r"(a) : "l"(p));
    return a;
}
__device__ __forceinline__ void cp16(uint32_t dst, const void* src) {
    asm volatile("cp.async.cg.shared.global [%0], [%1], 16;" :: "r"(dst), "l"(src));
}
#define CP_COMMIT() asm volatile("cp.async.commit_group;" ::: "memory")
#define CP_WAIT2()  asm volatile("cp.async.wait_group 2;" ::: "memory")

__device__ __forceinline__ uint32_t packh(float a, float b) {
    __half2 h = __floats2half2_rn(a, b);
    return *(uint32_t*)&h;
}
__device__ __forceinline__ void mma_f16(float* d, const uint32_t* a, const uint32_t* b) {
    asm volatile(
        "mma.sync.aligned.m16n8k16.row.col.f32.f16.f16.f32 "
        "{%0,%1,%2,%3}, {%4,%5,%6,%7}, {%8,%9}, {%0,%1,%2,%3};"
        : "+f"(d[0]), "+f"(d[1]), "+f"(d[2]), "+f"(d[3])
        : "r"(a[0]), "r"(a[1]), "r"(a[2]), "r"(a[3]), "r"(b[0]), "r"(b[1]));
}
__device__ __forceinline__ void ldsm_x4(uint32_t* r, uint32_t addr) {
    asm volatile("ldmatrix.sync.aligned.m8n8.x4.shared.b16 {%0,%1,%2,%3}, [%4];"
                 : "=r"(r[0]), "=r"(r[1]), "=r"(r[2]), "=r"(r[3]) : "r"(addr));
}
__device__ __forceinline__ void ldsm_x2_t(uint32_t& r0, uint32_t& r1, uint32_t addr) {
    asm volatile("ldmatrix.sync.aligned.m8n8.x2.trans.shared.b16 {%0,%1}, [%2];"
                 : "=r"(r0), "=r"(r1) : "r"(addr));
}
__device__ __forceinline__ float gelu_exact(float x) {
    return 0.5f * x * (1.0f + erff(x * 0.70710678118654752f));
}

// ---------------- streaming fp32 -> half convert -----------------------------
__global__ void __launch_bounds__(256) cvt_h(const float* __restrict__ in,
                                             __half* __restrict__ out) {
    size_t i = ((size_t)blockIdx.x * 256 + threadIdx.x) * 8;
    float4 a = *(const float4*)&in[i];
    float4 b = *(const float4*)&in[i + 4];
    uint4 o;
    o.x = packh(a.x, a.y); o.y = packh(a.z, a.w);
    o.z = packh(b.x, b.y); o.w = packh(b.z, b.w);
    *(uint4*)&out[i] = o;
}

// ---------------- LayerNorm fp32 in -> half out -------------------------------
__global__ void __launch_bounds__(256) ln_kernel(const float* __restrict__ x,
                                                 const float* __restrict__ g,
                                                 const float* __restrict__ b,
                                                 __half* __restrict__ out) {
    int row = blockIdx.x;
    int tid = threadIdx.x;
    const float* xr = x + (size_t)row * Dq;
    float4 v = *(const float4*)&xr[tid * 4];
    float sum = v.x + v.y + v.z + v.w;
    float sq  = v.x*v.x + v.y*v.y + v.z*v.z + v.w*v.w;
    #pragma unroll
    for (int o = 16; o; o >>= 1) {
        sum += __shfl_xor_sync(0xffffffffu, sum, o);
        sq  += __shfl_xor_sync(0xffffffffu, sq,  o);
    }
    __shared__ float red0[8], red1[8];
    int wid = tid >> 5, lane = tid & 31;
    if (lane == 0) { red0[wid] = sum; red1[wid] = sq; }
    __syncthreads();
    float tot = 0.f, totq = 0.f;
    #pragma unroll
    for (int i = 0; i < 8; i++) { tot += red0[i]; totq += red1[i]; }
    float mu  = tot * (1.0f / Dq);
    float var = totq * (1.0f / Dq) - mu * mu;
    float inv = rsqrtf(var + 1e-5f);
    float4 gv = *(const float4*)&g[tid * 4];
    float4 bv = *(const float4*)&b[tid * 4];
    uint2 o2;
    o2.x = packh((v.x - mu) * inv * gv.x + bv.x, (v.y - mu) * inv * gv.y + bv.y);
    o2.y = packh((v.z - mu) * inv * gv.z + bv.z, (v.w - mu) * inv * gv.w + bv.w);
    *(uint2*)&out[(size_t)row * Dq + tid * 4] = o2;
}

// ---------------- FP16 GEMM: 256x128 block, 64x64 warp tile, BK=32 ----------
// A half [M][K]; B half [K][N] (original layout). 256 threads, warp grid 4x2.
// A-frags ldmatrix.x4, B-frags ldmatrix.x2.trans. 4-stage cp.async.
// smem/stage: A 256x40 halves (20480B) at 0; B 32x136 halves (8704B) at 20480.
// EPI: 1 bias+gelu (half C), 2 +res (fp32), 3 bias+res (fp32), 4 rope (half C).
#define STAGE_B 29184
#define GEMM_SMEM_BYTES (4 * STAGE_B)
template <int EPI>
__global__ void __launch_bounds__(256) hgemm(const __half* __restrict__ A,
                                             const __half* __restrict__ B,
                                             const float* __restrict__ bias,
                                             const float* __restrict__ res,
                                             void* __restrict__ Cv,
                                             int N, int K) {
    extern __shared__ char smc[];
    const uint32_t sbase = smem_u32(smc);
    const int tid  = threadIdx.x;
    const int warp = tid >> 5, lane = tid & 31;
    const int gid  = lane >> 2, tig = lane & 3;
    const int wm   = warp >> 1, wn = warp & 1;
    const int m_w  = wm * 64,   n_w = wn * 64;
    const int bm   = blockIdx.y, bn = blockIdx.x;

    // ---- cp.async mappings ----
    // A: thread -> row tid (256 rows), 4 cp16 covering 32 halves
    const __half* Ar = A + (size_t)(bm * 256 + tid) * K;
    const uint32_t aDst = sbase + tid * 80;
    // B: slot tid -> (row tid>>4, col (tid&15)*8); second slot +16 rows
    const __half* Br0 = B + (size_t)(tid >> 4) * N + bn * 128 + (tid & 15) * 8;
    const uint32_t bDst = sbase + 20480 + (tid >> 4) * 272 + (tid & 15) * 16;

    // ---- ldmatrix per-lane base addresses ----
    const uint32_t a_base = sbase
        + ((m_w + ((lane >> 3) & 1) * 8 + (lane & 7)) * 40 + (lane >> 4) * 8) * 2;
    const uint32_t b_base = sbase + 20480 + ((lane & 15) * 136 + n_w) * 2;

    float acc[4][8][4];
    #pragma unroll
    for (int i = 0; i < 4; i++)
        #pragma unroll
        for (int j = 0; j < 8; j++)
            #pragma unroll
            for (int c = 0; c < 4; c++) acc[i][j][c] = 0.f;

    const int niter = K >> 5;
    #pragma unroll
    for (int s = 0; s < 3; s++) {
        const int k0 = s << 5;
        const uint32_t ab = aDst + s * STAGE_B;
        const __half* as = Ar + k0;
        cp16(ab,      as);
        cp16(ab + 16, as + 8);
        cp16(ab + 32, as + 16);
        cp16(ab + 48, as + 24);
        const uint32_t bb = bDst + s * STAGE_B;
        const __half* bs = Br0 + (size_t)k0 * N;
        cp16(bb,        bs);
        cp16(bb + 4352, bs + (size_t)16 * N);
        CP_COMMIT();
    }

    for (int kt = 0; kt < niter; kt++) {
        CP_WAIT2();
        __syncthreads();
        const int s = kt & 3;
        if (kt + 3 < niter) {
            const int sn = (kt + 3) & 3;
            const int k0 = (kt + 3) << 5;
            const uint32_t ab = aDst + sn * STAGE_B;
            const __half* as = Ar + k0;
            cp16(ab,      as);
            cp16(ab + 16, as + 8);
            cp16(ab + 32, as + 16);
            cp16(ab + 48, as + 24);
            const uint32_t bb = bDst + sn * STAGE_B;
            const __half* bs = Br0 + (size_t)k0 * N;
            cp16(bb,        bs);
            cp16(bb + 4352, bs + (size_t)16 * N);
        }
        CP_COMMIT();

        const uint32_t aS = a_base + s * STAGE_B;
        const uint32_t bS = b_base + s * STAGE_B;
        #pragma unroll
        for (int kk = 0; kk < 2; kk++) {
            uint32_t afr[4][4];
            const uint32_t aK = aS + kk * 32;          // +16 halves
            #pragma unroll
            for (int mt = 0; mt < 4; mt++)
                ldsm_x4(afr[mt], aK + mt * 16 * 80);   // 16 rows x 80 B
            uint32_t bfr[8][2];
            const uint32_t bK = bS + kk * 16 * 272;    // 16 k-rows x 272 B
            #pragma unroll
            for (int nt = 0; nt < 8; nt++)
                ldsm_x2_t(bfr[nt][0], bfr[nt][1], bK + nt * 16);
            #pragma unroll
            for (int mt = 0; mt < 4; mt++)
                #pragma unroll
                for (int nt = 0; nt < 8; nt++)
                    mma_f16(acc[mt][nt], afr[mt], bfr[nt]);
        }
    }

    // epilogue (res doubles as rope_freqs pointer for EPI==4)
    const bool do_rope = (EPI == 4) && (bn < 16);
    #pragma unroll
    for (int mt = 0; mt < 4; mt++) {
        int row0 = bm * 256 + m_w + mt * 16 + gid;
        #pragma unroll
        for (int nt = 0; nt < 8; nt++) {
            int col = bn * 128 + n_w + nt * 8 + tig * 2;
            #pragma unroll
            for (int half_ = 0; half_ < 2; half_++) {
                int r = row0 + half_ * 8;
                float r0 = acc[mt][nt][half_ * 2 + 0];
                float r1 = acc[mt][nt][half_ * 2 + 1];
                if (EPI == 1 || EPI == 3) {
                    r0 += bias[col];
                    r1 += bias[col + 1];
                }
                size_t base = (size_t)r * N + col;
                if (EPI == 1) {
                    r0 = gelu_exact(r0); r1 = gelu_exact(r1);
                    *(uint32_t*)&((__half*)Cv)[base] = packh(r0, r1);
                } else if (EPI == 4) {
                    if (do_rope) {
                        int t = (col & 63) >> 1;
                        float2 cs = *(const float2*)&res[((size_t)r * 32 + t) * 2];
                        float a = r0, bb2 = r1;
                        r0 = a * cs.x - bb2 * cs.y;
                        r1 = a * cs.y + bb2 * cs.x;
                    }
                    *(uint32_t*)&((__half*)Cv)[base] = packh(r0, r1);
                } else {
                    if (EPI == 2 || EPI == 3) {
                        float2 rv = *(const float2*)&res[base];
                        r0 += rv.x; r1 += rv.y;
                    }
                    *(float2*)&((float*)Cv)[base] = make_float2(r0, r1);
                }
            }
        }
    }
}

// ---------------- Attention: fp16 flash, register P, ldmatrix V --------------
__global__ void __launch_bounds__(256) attn_kernel() {
    __shared__ __half Ks[64 * 72];
    __shared__ __half Vs[64 * 72];

    const int qt = blockIdx.x, head = blockIdx.y, seg = blockIdx.z;
    const int tid = threadIdx.x, warp = tid >> 5, lane = tid & 31;
    const int gid = lane >> 2, tig = lane & 3;
    const int q0 = seg * 1024 + qt * 128;
    const int wrow = warp * 16;
    const float scale = 0.125f;

    uint32_t qf[4][4];
    {
        const __half* Q0 = g_qkvh + (size_t)(q0 + wrow + gid) * (3 * Dq) + head * HDq;
        const __half* Q1 = Q0 + (size_t)8 * (3 * Dq);
        #pragma unroll
        for (int kk = 0; kk < 4; kk++) {
            int kb = kk * 16 + 2 * tig;
            qf[kk][0] = *(const uint32_t*)&Q0[kb];
            qf[kk][1] = *(const uint32_t*)&Q1[kb];
            qf[kk][2] = *(const uint32_t*)&Q0[kb + 8];
            qf[kk][3] = *(const uint32_t*)&Q1[kb + 8];
        }
    }
    const uint32_t vrow = smem_u32(&Vs[(lane & 15) * 72]);

    float o[8][4];
    #pragma unroll
    for (int nt = 0; nt < 8; nt++)
        #pragma unroll
        for (int j = 0; j < 4; j++) o[nt][j] = 0.f;
    float m0 = -1e30f, m1 = -1e30f, l0 = 0.f, l1 = 0.f;

    for (int chn = 0; chn < 16; chn++) {
        __syncthreads();
        #pragma unroll
        for (int i = 0; i < 2; i++) {
            int slot = i * 256 + tid;
            int key = slot >> 3, d8 = (slot & 7) * 8;
            const __half* base = g_qkvh + (size_t)(seg * 1024 + chn * 64 + key) * (3 * Dq)
                               + head * HDq + d8;
            *(uint4*)&Ks[key * 72 + d8] = *(const uint4*)(base + Dq);
            *(uint4*)&Vs[key * 72 + d8] = *(const uint4*)(base + 2 * Dq);
        }
        __syncthreads();

        float s[8][4];
        #pragma unroll
        for (int nt = 0; nt < 8; nt++)
            #pragma unroll
            for (int j = 0; j < 4; j++) s[nt][j] = 0.f;
        #pragma unroll
        for (int kk = 0; kk < 4; kk++) {
            const int kb = kk * 16 + 2 * tig;
            #pragma unroll
            for (int nt = 0; nt < 8; nt++) {
                const int c0 = (nt * 8 + gid) * 72;
                uint32_t bb[2];
                bb[0] = *(const uint32_t*)&Ks[c0 + kb];
                bb[1] = *(const uint32_t*)&Ks[c0 + kb + 8];
                mma_f16(s[nt], qf[kk], bb);
            }
        }
        #pragma unroll
        for (int nt = 0; nt < 8; nt++) {
            s[nt][0] *= scale; s[nt][1] *= scale;
            s[nt][2] *= scale; s[nt][3] *= scale;
        }

        float mc0 = -1e30f, mc1 = -1e30f;
        #pragma unroll
        for (int nt = 0; nt < 8; nt++) {
            mc0 = fmaxf(mc0, fmaxf(s[nt][0], s[nt][1]));
            mc1 = fmaxf(mc1, fmaxf(s[nt][2], s[nt][3]));
        }
        mc0 = fmaxf(mc0, __shfl_xor_sync(0xffffffffu, mc0, 1));
        mc0 = fmaxf(mc0, __shfl_xor_sync(0xffffffffu, mc0, 2));
        mc1 = fmaxf(mc1, __shfl_xor_sync(0xffffffffu, mc1, 1));
        mc1 = fmaxf(mc1, __shfl_xor_sync(0xffffffffu, mc1, 2));
        float mn0 = fmaxf(m0, mc0), mn1 = fmaxf(m1, mc1);
        float c0 = __expf(m0 - mn0), c1 = __expf(m1 - mn1);
        m0 = mn0; m1 = mn1;
        l0 *= c0;  l1 *= c1;
        #pragma unroll
        for (int nt = 0; nt < 8; nt++) {
            o[nt][0] *= c0; o[nt][1] *= c0;
            o[nt][2] *= c1; o[nt][3] *= c1;
        }

        uint32_t uf[8][2];
        #pragma unroll
        for (int nt = 0; nt < 8; nt++) {
            float p0 = __expf(s[nt][0] - mn0);
            float p1 = __expf(s[nt][1] - mn0);
            float p2 = __expf(s[nt][2] - mn1);
            float p3 = __expf(s[nt][3] - mn1);
            uf[nt][0] = packh(p0, p1);
            uf[nt][1] = packh(p2, p3);
            __half2 h01 = *(__half2*)&uf[nt][0];
            __half2 h23 = *(__half2*)&uf[nt][1];
            l0 += __half2float(h01.x) + __half2float(h01.y);
            l1 += __half2float(h23.x) + __half2float(h23.y);
        }

        #pragma unroll
        for (int kk = 0; kk < 4; kk++) {
            uint32_t af[4] = { uf[2*kk][0], uf[2*kk][1], uf[2*kk+1][0], uf[2*kk+1][1] };
            const uint32_t kbase = vrow + kk * 16 * 144;
            #pragma unroll
            for (int nt = 0; nt < 8; nt++) {
                uint32_t bb[2];
                ldsm_x2_t(bb[0], bb[1], kbase + nt * 16);
                mma_f16(o[nt], af, bb);
            }
        }
    }

    l0 += __shfl_xor_sync(0xffffffffu, l0, 1);
    l0 += __shfl_xor_sync(0xffffffffu, l0, 2);
    l1 += __shfl_xor_sync(0xffffffffu, l1, 1);
    l1 += __shfl_xor_sync(0xffffffffu, l1, 2);
    float inv0 = 1.0f / l0, inv1 = 1.0f / l1;

    __half* O0 = g_attnh + (size_t)(q0 + wrow + gid) * Dq + head * HDq;
    __half* O1 = O0 + (size_t)8 * Dq;
    #pragma unroll
    for (int nt = 0; nt < 8; nt++) {
        *(uint32_t*)&O0[nt * 8 + tig * 2] = packh(o[nt][0] * inv0, o[nt][1] * inv0);
        *(uint32_t*)&O1[nt * 8 + tig * 2] = packh(o[nt][2] * inv1, o[nt][3] * inv1);
    }
}

// ---------------- host orchestration ---------------------------------------
extern "C" void kernel_launch(void* const* d_in, const int* in_sizes, int n_in,
                              void* d_out, int out_size) {
    const float* hidden = (const float*)d_in[0];
    const float* rope   = (const float*)d_in[2];
    const float* ln0_g  = (const float*)d_in[3];
    const float* ln0_b  = (const float*)d_in[4];
    const float* ln1_g  = (const float*)d_in[5];
    const float* ln1_b  = (const float*)d_in[6];
    const float* w_qkv  = (const float*)d_in[7];
    const float* w_o    = (const float*)d_in[8];
    const float* w_fc0  = (const float*)d_in[9];
    const float* b_fc0  = (const float*)d_in[10];
    const float* w_fc1  = (const float*)d_in[11];
    const float* b_fc1  = (const float*)d_in[12];
    float* out = (float*)d_out;

    float  *p_h;
    __half *p_qkvh, *p_xlnh, *p_ylnh, *p_attnh, *p_fc0h;
    __half *p_wqkvc, *p_woc, *p_fc0c, *p_fc1c;
    cudaGetSymbolAddress((void**)&p_h,     g_h);
    cudaGetSymbolAddress((void**)&p_qkvh,  g_qkvh);
    cudaGetSymbolAddress((void**)&p_xlnh,  g_xlnh);
    cudaGetSymbolAddress((void**)&p_ylnh,  g_ylnh);
    cudaGetSymbolAddress((void**)&p_attnh, g_attnh);
    cudaGetSymbolAddress((void**)&p_fc0h,  g_fc0h);
    cudaGetSymbolAddress((void**)&p_wqkvc, g_wqkvc);
    cudaGetSymbolAddress((void**)&p_woc,   g_woc);
    cudaGetSymbolAddress((void**)&p_fc0c,  g_fc0c);
    cudaGetSymbolAddress((void**)&p_fc1c,  g_fc1c);

    cudaFuncSetAttribute(hgemm<1>, cudaFuncAttributeMaxDynamicSharedMemorySize, GEMM_SMEM_BYTES);
    cudaFuncSetAttribute(hgemm<2>, cudaFuncAttributeMaxDynamicSharedMemorySize, GEMM_SMEM_BYTES);
    cudaFuncSetAttribute(hgemm<3>, cudaFuncAttributeMaxDynamicSharedMemorySize, GEMM_SMEM_BYTES);
    cudaFuncSetAttribute(hgemm<4>, cudaFuncAttributeMaxDynamicSharedMemorySize, GEMM_SMEM_BYTES);

    // 0. weight converts fp32 -> half (layout preserved [K][N])
    cvt_h<<<(Dq * 3 * Dq) / 2048, 256>>>(w_qkv, p_wqkvc);
    cvt_h<<<(Dq * Dq) / 2048, 256>>>(w_o,   p_woc);
    cvt_h<<<(Dq * Mq) / 2048, 256>>>(w_fc0, p_fc0c);
    cvt_h<<<(Mq * Dq) / 2048, 256>>>(w_fc1, p_fc1c);

    // 1. LN0 -> half
    ln_kernel<<<Lq, 256>>>(hidden, ln0_g, ln0_b, p_xlnh);
    // 2. QKV = xln @ w_qkv, rope fused -> half
    hgemm<4><<<dim3(3 * Dq / 128, Lq / 256), 256, GEMM_SMEM_BYTES>>>(
        p_xlnh, p_wqkvc, nullptr, rope, p_qkvh, 3 * Dq, Dq);
    // 3. Attention -> half
    attn_kernel<<<dim3(8, Hq, 4), 256>>>();
    // 4. h = hidden + attn @ w_o -> fp32
    hgemm<2><<<dim3(Dq / 128, Lq / 256), 256, GEMM_SMEM_BYTES>>>(
        p_attnh, p_woc, nullptr, hidden, p_h, Dq, Dq);
    // 5. LN1 -> half
    ln_kernel<<<Lq, 256>>>(p_h, ln1_g, ln1_b, p_ylnh);
    // 6. fc0 + bias + gelu -> half
    hgemm<1><<<dim3(Mq / 128, Lq / 256), 256, GEMM_SMEM_BYTES>>>(
        p_ylnh, p_fc0c, b_fc0, nullptr, p_fc0h, Mq, Dq);
    // 7. out = h + fc0g @ w_fc1 + b_fc1 -> fp32
    hgemm<3><<<dim3(Dq / 128, Lq / 256), 256, GEMM_SMEM_BYTES>>>(
        p_fc0h, p_fc1c, b_fc1, p_h, out, Dq, Mq);
    (void)in_sizes; (void)n_in; (void)out_size;
}

// round 9
// speedup vs baseline: 1.1195x; 1.1195x over previous
#include <cuda_runtime.h>
#include <cuda_fp16.h>
#include <math.h>
#include <stdint.h>

#define Lq 4096
#define Dq 1024
#define Hq 16
#define HDq 64
#define Mq 4096

// ---------------- scratch (device globals; no allocation allowed) ----------
__device__ float  g_h    [Lq*Dq];            // fp32 residual+attn@w_o
__device__ __half g_qkvh [Lq*3*Dq];          // half qkv (rope fused in epilogue)
__device__ __half g_xlnh [Lq*Dq];
__device__ __half g_ylnh [Lq*Dq];
__device__ __half g_attnh[Lq*Dq];
__device__ __half g_fc0h [(size_t)Lq*Mq];
// half weights, original [K][N] layout (convert only, no transpose)
__device__ __half g_wqkvc[Dq*3*Dq];
__device__ __half g_woc  [Dq*Dq];
__device__ __half g_fc0c [(size_t)Dq*Mq];
__device__ __half g_fc1c [(size_t)Mq*Dq];

// ---------------- helpers ----------------------------------------------------
__device__ __forceinline__ uint32_t smem_u32(const void* p) {
    uint32_t a;
    asm("{ .reg .u64 t; cvta.to.shared.u64 t, %1; cvt.u32.u64 %0, t; }" : "=r"(a) : "l"(p));
    return a;
}
__device__ __forceinline__ void cp16(uint32_t dst, const void* src) {
    asm volatile("cp.async.cg.shared.global [%0], [%1], 16;" :: "r"(dst), "l"(src));
}
#define CP_COMMIT() asm volatile("cp.async.commit_group;" ::: "memory")
#define CP_WAIT2()  asm volatile("cp.async.wait_group 2;" ::: "memory")
#define CP_WAIT1()  asm volatile("cp.async.wait_group 1;" ::: "memory")
#define CP_WAIT0()  asm volatile("cp.async.wait_group 0;" ::: "memory")

__device__ __forceinline__ uint32_t packh(float a, float b) {
    __half2 h = __floats2half2_rn(a, b);
    return *(uint32_t*)&h;
}
__device__ __forceinline__ void mma_f16(float* d, const uint32_t* a, const uint32_t* b) {
    asm volatile(
        "mma.sync.aligned.m16n8k16.row.col.f32.f16.f16.f32 "
        "{%0,%1,%2,%3}, {%4,%5,%6,%7}, {%8,%9}, {%0,%1,%2,%3};"
        : "+f"(d[0]), "+f"(d[1]), "+f"(d[2]), "+f"(d[3])
        : "r"(a[0]), "r"(a[1]), "r"(a[2]), "r"(a[3]), "r"(b[0]), "r"(b[1]));
}
__device__ __forceinline__ void ldsm_x4(uint32_t* r, uint32_t addr) {
    asm volatile("ldmatrix.sync.aligned.m8n8.x4.shared.b16 {%0,%1,%2,%3}, [%4];"
                 : "=r"(r[0]), "=r"(r[1]), "=r"(r[2]), "=r"(r[3]) : "r"(addr));
}
__device__ __forceinline__ void ldsm_x2_t(uint32_t& r0, uint32_t& r1, uint32_t addr) {
    asm volatile("ldmatrix.sync.aligned.m8n8.x2.trans.shared.b16 {%0,%1}, [%2];"
                 : "=r"(r0), "=r"(r1) : "r"(addr));
}
__device__ __forceinline__ float gelu_exact(float x) {
    return 0.5f * x * (1.0f + erff(x * 0.70710678118654752f));
}

// ---------------- fused streaming fp32 -> half convert (4 arrays) ------------
// blocks: [0,1536) qkv, [1536,2048) w_o, [2048,4096) fc0, [4096,6144) fc1
__global__ void __launch_bounds__(256) cvt_all(const float* __restrict__ w0, __half* __restrict__ o0,
                                               const float* __restrict__ w1, __half* __restrict__ o1,
                                               const float* __restrict__ w2, __half* __restrict__ o2,
                                               const float* __restrict__ w3, __half* __restrict__ o3) {
    int blk = blockIdx.x;
    const float* in; __half* out; size_t off;
    if (blk < 1536)      { in = w0; out = o0; off = (size_t)blk * 2048; }
    else if (blk < 2048) { in = w1; out = o1; off = (size_t)(blk - 1536) * 2048; }
    else if (blk < 4096) { in = w2; out = o2; off = (size_t)(blk - 2048) * 2048; }
    else                 { in = w3; out = o3; off = (size_t)(blk - 4096) * 2048; }
    size_t i = off + (size_t)threadIdx.x * 8;
    float4 a = *(const float4*)&in[i];
    float4 b = *(const float4*)&in[i + 4];
    uint4 o;
    o.x = packh(a.x, a.y); o.y = packh(a.z, a.w);
    o.z = packh(b.x, b.y); o.w = packh(b.z, b.w);
    *(uint4*)&out[i] = o;
}

// ---------------- LayerNorm fp32 in -> half out -------------------------------
__global__ void __launch_bounds__(256) ln_kernel(const float* __restrict__ x,
                                                 const float* __restrict__ g,
                                                 const float* __restrict__ b,
                                                 __half* __restrict__ out) {
    int row = blockIdx.x;
    int tid = threadIdx.x;
    const float* xr = x + (size_t)row * Dq;
    float4 v = *(const float4*)&xr[tid * 4];
    float sum = v.x + v.y + v.z + v.w;
    float sq  = v.x*v.x + v.y*v.y + v.z*v.z + v.w*v.w;
    #pragma unroll
    for (int o = 16; o; o >>= 1) {
        sum += __shfl_xor_sync(0xffffffffu, sum, o);
        sq  += __shfl_xor_sync(0xffffffffu, sq,  o);
    }
    __shared__ float red0[8], red1[8];
    int wid = tid >> 5, lane = tid & 31;
    if (lane == 0) { red0[wid] = sum; red1[wid] = sq; }
    __syncthreads();
    float tot = 0.f, totq = 0.f;
    #pragma unroll
    for (int i = 0; i < 8; i++) { tot += red0[i]; totq += red1[i]; }
    float mu  = tot * (1.0f / Dq);
    float var = totq * (1.0f / Dq) - mu * mu;
    float inv = rsqrtf(var + 1e-5f);
    float4 gv = *(const float4*)&g[tid * 4];
    float4 bv = *(const float4*)&b[tid * 4];
    uint2 o2;
    o2.x = packh((v.x - mu) * inv * gv.x + bv.x, (v.y - mu) * inv * gv.y + bv.y);
    o2.y = packh((v.z - mu) * inv * gv.z + bv.z, (v.w - mu) * inv * gv.w + bv.w);
    *(uint2*)&out[(size_t)row * Dq + tid * 4] = o2;
}

// ---------------- FP16 GEMM: 128x128 tile, BK=32, 4-stage, ldmatrix ---------
// (round-7 config: 8 warps, 64x32 warp tiles, 2 CTAs/SM)
#define GEMM_SMEM_BYTES (40960 + 4*8704)
template <int EPI>
__global__ void __launch_bounds__(256) hgemm(const __half* __restrict__ A,
                                             const __half* __restrict__ B,
                                             const float* __restrict__ bias,
                                             const float* __restrict__ res,
                                             void* __restrict__ Cv,
                                             int N, int K) {
    extern __shared__ char smc[];
    const uint32_t sbase = smem_u32(smc);
    const int tid  = threadIdx.x;
    const int warp = tid >> 5, lane = tid & 31;
    const int gid  = lane >> 2, tig = lane & 3;
    const int wm   = warp >> 2, wn = warp & 3;
    const int m_w  = wm * 64,   n_w = wn * 32;
    const int bm   = blockIdx.y, bn = blockIdx.x;

    const int arow = tid >> 1;
    const int ch0  = (tid & 1) * 8;
    const __half* Ar = A + (size_t)(bm * 128 + arow) * K;
    const int brow = tid >> 3;
    const int bc0  = (tid & 7) * 16;
    const __half* Br = B + (size_t)brow * N + bn * 128 + bc0;

    uint32_t dA[4][2], dB[4][2];
    #pragma unroll
    for (int s = 0; s < 4; s++) {
        dA[s][0] = sbase + s * 10240 + (arow * 40 + ch0) * 2;
        dA[s][1] = dA[s][0] + 32;
        dB[s][0] = sbase + 40960 + s * 8704 + (brow * 136 + bc0) * 2;
        dB[s][1] = dB[s][0] + 16;
    }

    const uint32_t a_base = sbase
        + ((m_w + ((lane >> 3) & 1) * 8 + (lane & 7)) * 40 + (lane >> 4) * 8) * 2;
    const uint32_t b_base = sbase + 40960 + ((lane & 15) * 136 + n_w) * 2;

    float acc[4][4][4];
    #pragma unroll
    for (int i = 0; i < 4; i++)
        #pragma unroll
        for (int j = 0; j < 4; j++)
            #pragma unroll
            for (int c = 0; c < 4; c++) acc[i][j][c] = 0.f;

    const int niter = K >> 5;
    #pragma unroll
    for (int s = 0; s < 3; s++) {
        int k0 = s * 32;
        cp16(dA[s][0], Ar + k0 + ch0);
        cp16(dA[s][1], Ar + k0 + ch0 + 16);
        cp16(dB[s][0], Br + (size_t)k0 * N);
        cp16(dB[s][1], Br + (size_t)k0 * N + 8);
        CP_COMMIT();
    }

    for (int kt = 0; kt < niter; kt++) {
        CP_WAIT2();
        __syncthreads();
        const int s = kt & 3;
        if (kt + 3 < niter) {
            const int sn = (kt + 3) & 3;
            const int k0 = (kt + 3) << 5;
            cp16(dA[sn][0], Ar + k0 + ch0);
            cp16(dA[sn][1], Ar + k0 + ch0 + 16);
            cp16(dB[sn][0], Br + (size_t)k0 * N);
            cp16(dB[sn][1], Br + (size_t)k0 * N + 8);
        }
        CP_COMMIT();

        const uint32_t aS = a_base + s * 10240;
        const uint32_t bS = b_base + s * 8704;
        #pragma unroll
        for (int kk = 0; kk < 2; kk++) {
            uint32_t afr[4][4];
            const uint32_t aK = aS + kk * 32;
            #pragma unroll
            for (int mt = 0; mt < 4; mt++)
                ldsm_x4(afr[mt], aK + mt * 16 * 80);
            uint32_t bfr[4][2];
            const uint32_t bK = bS + kk * 16 * 272;
            #pragma unroll
            for (int nt = 0; nt < 4; nt++)
                ldsm_x2_t(bfr[nt][0], bfr[nt][1], bK + nt * 16);
            #pragma unroll
            for (int mt = 0; mt < 4; mt++)
                #pragma unroll
                for (int nt = 0; nt < 4; nt++)
                    mma_f16(acc[mt][nt], afr[mt], bfr[nt]);
        }
    }

    const bool do_rope = (EPI == 4) && (bn < 16);
    #pragma unroll
    for (int mt = 0; mt < 4; mt++) {
        int row0 = bm * 128 + m_w + mt * 16 + gid;
        #pragma unroll
        for (int nt = 0; nt < 4; nt++) {
            int col = bn * 128 + n_w + nt * 8 + tig * 2;
            #pragma unroll
            for (int half_ = 0; half_ < 2; half_++) {
                int r = row0 + half_ * 8;
                float r0 = acc[mt][nt][half_ * 2 + 0];
                float r1 = acc[mt][nt][half_ * 2 + 1];
                if (EPI == 1 || EPI == 3) {
                    r0 += bias[col];
                    r1 += bias[col + 1];
                }
                size_t base = (size_t)r * N + col;
                if (EPI == 1) {
                    r0 = gelu_exact(r0); r1 = gelu_exact(r1);
                    *(uint32_t*)&((__half*)Cv)[base] = packh(r0, r1);
                } else if (EPI == 4) {
                    if (do_rope) {
                        int t = (col & 63) >> 1;
                        float2 cs = *(const float2*)&res[((size_t)r * 32 + t) * 2];
                        float a = r0, bb2 = r1;
                        r0 = a * cs.x - bb2 * cs.y;
                        r1 = a * cs.y + bb2 * cs.x;
                    }
                    *(uint32_t*)&((__half*)Cv)[base] = packh(r0, r1);
                } else {
                    if (EPI == 2 || EPI == 3) {
                        float2 rv = *(const float2*)&res[base];
                        r0 += rv.x; r1 += rv.y;
                    }
                    *(float2*)&((float*)Cv)[base] = make_float2(r0, r1);
                }
            }
        }
    }
}

// ---------------- Attention: fp16 flash, cp.async double-buffered K/V --------
__global__ void __launch_bounds__(256) attn_kernel() {
    __shared__ __half Ks[2][64 * 72];
    __shared__ __half Vs[2][64 * 72];

    const int qt = blockIdx.x, head = blockIdx.y, seg = blockIdx.z;
    const int tid = threadIdx.x, warp = tid >> 5, lane = tid & 31;
    const int gid = lane >> 2, tig = lane & 3;
    const int q0 = seg * 1024 + qt * 128;
    const int wrow = warp * 16;
    const float scale = 0.125f;

    // per-thread K/V cp.async mapping: 2 slots, each 8 halves of K and of V
    const int key0 = tid >> 3, d8 = (tid & 7) * 8;
    const __half* kvsrc0 = g_qkvh + (size_t)(seg * 1024 + key0) * (3 * Dq) + head * HDq + d8;
    const __half* kvsrc1 = kvsrc0 + (size_t)32 * (3 * Dq);   // key0 + 32
    uint32_t kdst0[2], kdst1[2], vdst0[2], vdst1[2];
    #pragma unroll
    for (int b = 0; b < 2; b++) {
        kdst0[b] = smem_u32(&Ks[b][key0 * 72 + d8]);
        kdst1[b] = smem_u32(&Ks[b][(key0 + 32) * 72 + d8]);
        vdst0[b] = smem_u32(&Vs[b][key0 * 72 + d8]);
        vdst1[b] = smem_u32(&Vs[b][(key0 + 32) * 72 + d8]);
    }

    uint32_t qf[4][4];
    {
        const __half* Q0 = g_qkvh + (size_t)(q0 + wrow + gid) * (3 * Dq) + head * HDq;
        const __half* Q1 = Q0 + (size_t)8 * (3 * Dq);
        #pragma unroll
        for (int kk = 0; kk < 4; kk++) {
            int kb = kk * 16 + 2 * tig;
            qf[kk][0] = *(const uint32_t*)&Q0[kb];
            qf[kk][1] = *(const uint32_t*)&Q1[kb];
            qf[kk][2] = *(const uint32_t*)&Q0[kb + 8];
            qf[kk][3] = *(const uint32_t*)&Q1[kb + 8];
        }
    }

    float o[8][4];
    #pragma unroll
    for (int nt = 0; nt < 8; nt++)
        #pragma unroll
        for (int j = 0; j < 4; j++) o[nt][j] = 0.f;
    float m0 = -1e30f, m1 = -1e30f, l0 = 0.f, l1 = 0.f;

    // issue chunk 0 into buf 0
    {
        const size_t off = 0;
        cp16(kdst0[0], kvsrc0 + off + Dq);
        cp16(kdst1[0], kvsrc1 + off + Dq);
        cp16(vdst0[0], kvsrc0 + off + 2 * Dq);
        cp16(vdst1[0], kvsrc1 + off + 2 * Dq);
        CP_COMMIT();
    }

    for (int chn = 0; chn < 16; chn++) {
        const int buf = chn & 1;
        if (chn + 1 < 16) {
            const size_t off = (size_t)(chn + 1) * 64 * (3 * Dq);
            cp16(kdst0[buf ^ 1], kvsrc0 + off + Dq);
            cp16(kdst1[buf ^ 1], kvsrc1 + off + Dq);
            cp16(vdst0[buf ^ 1], kvsrc0 + off + 2 * Dq);
            cp16(vdst1[buf ^ 1], kvsrc1 + off + 2 * Dq);
            CP_COMMIT();
            CP_WAIT1();
        } else {
            CP_WAIT0();
        }
        __syncthreads();

        const uint32_t vrow = smem_u32(&Vs[buf][(lane & 15) * 72]);

        float s[8][4];
        #pragma unroll
        for (int nt = 0; nt < 8; nt++)
            #pragma unroll
            for (int j = 0; j < 4; j++) s[nt][j] = 0.f;
        #pragma unroll
        for (int kk = 0; kk < 4; kk++) {
            const int kb = kk * 16 + 2 * tig;
            #pragma unroll
            for (int nt = 0; nt < 8; nt++) {
                const int c0 = (nt * 8 + gid) * 72;
                uint32_t bb[2];
                bb[0] = *(const uint32_t*)&Ks[buf][c0 + kb];
                bb[1] = *(const uint32_t*)&Ks[buf][c0 + kb + 8];
                mma_f16(s[nt], qf[kk], bb);
            }
        }
        #pragma unroll
        for (int nt = 0; nt < 8; nt++) {
            s[nt][0] *= scale; s[nt][1] *= scale;
            s[nt][2] *= scale; s[nt][3] *= scale;
        }

        float mc0 = -1e30f, mc1 = -1e30f;
        #pragma unroll
        for (int nt = 0; nt < 8; nt++) {
            mc0 = fmaxf(mc0, fmaxf(s[nt][0], s[nt][1]));
            mc1 = fmaxf(mc1, fmaxf(s[nt][2], s[nt][3]));
        }
        mc0 = fmaxf(mc0, __shfl_xor_sync(0xffffffffu, mc0, 1));
        mc0 = fmaxf(mc0, __shfl_xor_sync(0xffffffffu, mc0, 2));
        mc1 = fmaxf(mc1, __shfl_xor_sync(0xffffffffu, mc1, 1));
        mc1 = fmaxf(mc1, __shfl_xor_sync(0xffffffffu, mc1, 2));
        float mn0 = fmaxf(m0, mc0), mn1 = fmaxf(m1, mc1);
        float c0 = __expf(m0 - mn0), c1 = __expf(m1 - mn1);
        m0 = mn0; m1 = mn1;
        l0 *= c0;  l1 *= c1;
        #pragma unroll
        for (int nt = 0; nt < 8; nt++) {
            o[nt][0] *= c0; o[nt][1] *= c0;
            o[nt][2] *= c1; o[nt][3] *= c1;
        }

        uint32_t uf[8][2];
        #pragma unroll
        for (int nt = 0; nt < 8; nt++) {
            float p0 = __expf(s[nt][0] - mn0);
            float p1 = __expf(s[nt][1] - mn0);
            float p2 = __expf(s[nt][2] - mn1);
            float p3 = __expf(s[nt][3] - mn1);
            uf[nt][0] = packh(p0, p1);
            uf[nt][1] = packh(p2, p3);
            __half2 h01 = *(__half2*)&uf[nt][0];
            __half2 h23 = *(__half2*)&uf[nt][1];
            l0 += __half2float(h01.x) + __half2float(h01.y);
            l1 += __half2float(h23.x) + __half2float(h23.y);
        }

        #pragma unroll
        for (int kk = 0; kk < 4; kk++) {
            uint32_t af[4] = { uf[2*kk][0], uf[2*kk][1], uf[2*kk+1][0], uf[2*kk+1][1] };
            const uint32_t kbase = vrow + kk * 16 * 144;
            #pragma unroll
            for (int nt = 0; nt < 8; nt++) {
                uint32_t bb[2];
                ldsm_x2_t(bb[0], bb[1], kbase + nt * 16);
                mma_f16(o[nt], af, bb);
            }
        }
        __syncthreads();   // protect buf before it is overwritten next iteration
    }

    l0 += __shfl_xor_sync(0xffffffffu, l0, 1);
    l0 += __shfl_xor_sync(0xffffffffu, l0, 2);
    l1 += __shfl_xor_sync(0xffffffffu, l1, 1);
    l1 += __shfl_xor_sync(0xffffffffu, l1, 2);
    float inv0 = 1.0f / l0, inv1 = 1.0f / l1;

    __half* O0 = g_attnh + (size_t)(q0 + wrow + gid) * Dq + head * HDq;
    __half* O1 = O0 + (size_t)8 * Dq;
    #pragma unroll
    for (int nt = 0; nt < 8; nt++) {
        *(uint32_t*)&O0[nt * 8 + tig * 2] = packh(o[nt][0] * inv0, o[nt][1] * inv0);
        *(uint32_t*)&O1[nt * 8 + tig * 2] = packh(o[nt][2] * inv1, o[nt][3] * inv1);
    }
}

// ---------------- host orchestration ---------------------------------------
extern "C" void kernel_launch(void* const* d_in, const int* in_sizes, int n_in,
                              void* d_out, int out_size) {
    const float* hidden = (const float*)d_in[0];
    const float* rope   = (const float*)d_in[2];
    const float* ln0_g  = (const float*)d_in[3];
    const float* ln0_b  = (const float*)d_in[4];
    const float* ln1_g  = (const float*)d_in[5];
    const float* ln1_b  = (const float*)d_in[6];
    const float* w_qkv  = (const float*)d_in[7];
    const float* w_o    = (const float*)d_in[8];
    const float* w_fc0  = (const float*)d_in[9];
    const float* b_fc0  = (const float*)d_in[10];
    const float* w_fc1  = (const float*)d_in[11];
    const float* b_fc1  = (const float*)d_in[12];
    float* out = (float*)d_out;

    float  *p_h;
    __half *p_qkvh, *p_xlnh, *p_ylnh, *p_attnh, *p_fc0h;
    __half *p_wqkvc, *p_woc, *p_fc0c, *p_fc1c;
    cudaGetSymbolAddress((void**)&p_h,     g_h);
    cudaGetSymbolAddress((void**)&p_qkvh,  g_qkvh);
    cudaGetSymbolAddress((void**)&p_xlnh,  g_xlnh);
    cudaGetSymbolAddress((void**)&p_ylnh,  g_ylnh);
    cudaGetSymbolAddress((void**)&p_attnh, g_attnh);
    cudaGetSymbolAddress((void**)&p_fc0h,  g_fc0h);
    cudaGetSymbolAddress((void**)&p_wqkvc, g_wqkvc);
    cudaGetSymbolAddress((void**)&p_woc,   g_woc);
    cudaGetSymbolAddress((void**)&p_fc0c,  g_fc0c);
    cudaGetSymbolAddress((void**)&p_fc1c,  g_fc1c);

    cudaFuncSetAttribute(hgemm<1>, cudaFuncAttributeMaxDynamicSharedMemorySize, GEMM_SMEM_BYTES);
    cudaFuncSetAttribute(hgemm<2>, cudaFuncAttributeMaxDynamicSharedMemorySize, GEMM_SMEM_BYTES);
    cudaFuncSetAttribute(hgemm<3>, cudaFuncAttributeMaxDynamicSharedMemorySize, GEMM_SMEM_BYTES);
    cudaFuncSetAttribute(hgemm<4>, cudaFuncAttributeMaxDynamicSharedMemorySize, GEMM_SMEM_BYTES);

    // 0. weight converts fp32 -> half (single fused launch)
    cvt_all<<<6144, 256>>>(w_qkv, p_wqkvc, w_o, p_woc, w_fc0, p_fc0c, w_fc1, p_fc1c);

    // 1. LN0 -> half
    ln_kernel<<<Lq, 256>>>(hidden, ln0_g, ln0_b, p_xlnh);
    // 2. QKV = xln @ w_qkv, rope fused -> half
    hgemm<4><<<dim3(3 * Dq / 128, Lq / 128), 256, GEMM_SMEM_BYTES>>>(
        p_xlnh, p_wqkvc, nullptr, rope, p_qkvh, 3 * Dq, Dq);
    // 3. Attention -> half
    attn_kernel<<<dim3(8, Hq, 4), 256>>>();
    // 4. h = hidden + attn @ w_o -> fp32
    hgemm<2><<<dim3(Dq / 128, Lq / 128), 256, GEMM_SMEM_BYTES>>>(
        p_attnh, p_woc, nullptr, hidden, p_h, Dq, Dq);
    // 5. LN1 -> half
    ln_kernel<<<Lq, 256>>>(p_h, ln1_g, ln1_b, p_ylnh);
    // 6. fc0 + bias + gelu -> half
    hgemm<1><<<dim3(Mq / 128, Lq / 128), 256, GEMM_SMEM_BYTES>>>(
        p_ylnh, p_fc0c, b_fc0, nullptr, p_fc0h, Mq, Dq);
    // 7. out = h + fc0g @ w_fc1 + b_fc1 -> fp32
    hgemm<3><<<dim3(Dq / 128, Lq / 128), 256, GEMM_SMEM_BYTES>>>(
        p_fc0h, p_fc1c, b_fc1, p_h, out, Dq, Mq);
    (void)in_sizes; (void)n_in; (void)out_size;
}